// round 6
// baseline (speedup 1.0000x reference)
#include <cuda_runtime.h>
#include <stdint.h>

#define HH 512
#define WW 512
#define NB 4

typedef unsigned long long ull;

// Packed border tensor: 16 channels x 2 bits per pixel (values in {0,1,2}).
__device__ uint32_t g_border[NB * HH * WW];

__device__ __forceinline__ ull ffma2(ull a, ull b, ull c) {
    ull d;
    asm("fma.rn.f32x2 %0, %1, %2, %3;" : "=l"(d) : "l"(a), "l"(b), "l"(c));
    return d;
}
__device__ __forceinline__ ull pack2(float x, float y) {
    ull d;
    asm("mov.b64 %0, {%1, %2};" : "=l"(d) : "f"(x), "f"(y));
    return d;
}
__device__ __forceinline__ float2 unpack2(ull v) {
    float2 r;
    asm("mov.b64 {%0, %1}, %2;" : "=f"(r.x), "=f"(r.y) : "l"(v));
    return r;
}

// ---------------------------------------------------------------------------
// Stage 1: 11x11 conv (1->8 ch) on both input planes + spike/WTA logic.
// Planes (in0,in1) ride in one FFMA2. Duplicated weights stored [tap][filter]
// so each tap's 8 weights come from 4 broadcast LDS.128.
// Block (32,16), tile 32x32. Also zeroes d_out (stage2 accumulates via atomics).
// ---------------------------------------------------------------------------
__global__ __launch_bounds__(512)
void stage1_kernel(const float* __restrict__ inp, const float* __restrict__ Wb,
                   float* __restrict__ out)
{
    __shared__ ull s01[42][44];                  // (in0,in1) packed (14.8 KB)
    __shared__ __align__(16) ull dsh[121 * 8];   // dup weights [t][f] (7.7 KB)

    const int b  = blockIdx.z;
    const int x0 = blockIdx.x * 32;
    const int y0 = blockIdx.y * 32;
    const int tx = threadIdx.x;      // 0..31
    const int ty = threadIdx.y;      // 0..15
    const int tid = ty * 32 + tx;

    for (int i = tid; i < 968; i += 512) {
        int t = i >> 3, f = i & 7;
        float w = Wb[f * 121 + t];
        dsh[i] = pack2(w, w);
    }

    const float* __restrict__ in0 = inp + ((size_t)b * 2 + 0) * HH * WW;
    const float* __restrict__ in1 = inp + ((size_t)b * 2 + 1) * HH * WW;

    for (int ry = ty; ry < 42; ry += 16) {
        int gy = y0 - 5 + ry;
        for (int rx = tx; rx < 42; rx += 32) {
            int gx = x0 - 5 + rx;
            bool ok = ((unsigned)gy < HH) && ((unsigned)gx < WW);
            float v0 = ok ? in0[gy * WW + gx] : 0.0f;
            float v1 = ok ? in1[gy * WW + gx] : 0.0f;
            s01[ry][rx] = pack2(v0, v1);
        }
    }
    __syncthreads();

    ull acc0[8], acc1[8];            // .x = pos conv, .y = neg conv
    #pragma unroll
    for (int f = 0; f < 8; ++f) { acc0[f] = 0ull; acc1[f] = 0ull; }

    #pragma unroll 1
    for (int dy = 0; dy < 11; ++dy) {
        #pragma unroll
        for (int dx = 0; dx < 11; ++dx) {
            ull xa = s01[ty + dy][tx + dx];
            ull xb = s01[ty + 16 + dy][tx + dx];
            const int t = dy * 11 + dx;
            const ulonglong2* wp = (const ulonglong2*)&dsh[t * 8];
            #pragma unroll
            for (int fp = 0; fp < 4; ++fp) {
                ulonglong2 w2 = wp[fp];
                acc0[2*fp]   = ffma2(w2.x, xa, acc0[2*fp]);
                acc1[2*fp]   = ffma2(w2.x, xb, acc1[2*fp]);
                acc0[2*fp+1] = ffma2(w2.y, xa, acc0[2*fp+1]);
                acc1[2*fp+1] = ffma2(w2.y, xb, acc1[2*fp+1]);
            }
        }
    }

    #pragma unroll
    for (int k = 0; k < 2; ++k) {
        const int yy = ty + k * 16;
        float2 ctr = unpack2(s01[yy + 5][tx + 5]);
        float vm = ctr.x + ctr.y;

        int b13[4], b24[4];
        #pragma unroll
        for (int o = 0; o < 4; ++o) {
            float2 e = unpack2(k == 0 ? acc0[2*o]   : acc1[2*o]);
            float2 d = unpack2(k == 0 ? acc0[2*o+1] : acc1[2*o+1]);
            float pe = e.x >= 1.0f ? 1.0f : 0.0f;
            float ne = e.y >= 1.0f ? 1.0f : 0.0f;
            float po = d.x >= 1.0f ? 1.0f : 0.0f;
            float no = d.y >= 1.0f ? 1.0f : 0.0f;
            int s1 = (vm * (pe - 1.5f * no) >= 1.0f) ? 1 : 0;
            int s2 = (vm * (ne - 1.5f * po) >= 1.0f) ? 1 : 0;
            int s3 = (vm * (po - 1.5f * ne) >= 1.0f) ? 1 : 0;
            int s4 = (vm * (no - 1.5f * pe) >= 1.0f) ? 1 : 0;
            b13[o] = s1 + s2;
            b24[o] = s3 + s4;
        }

        int tmax = 0;
        #pragma unroll
        for (int o = 0; o < 4; ++o) {
            int d = b13[o] - b24[o];
            int tp = d < 0 ? -d : d;
            if (tp > tmax) tmax = tp;
        }

        uint32_t word = 0;
        #pragma unroll
        for (int o = 0; o < 4; ++o) {
            int d = b13[o] - b24[o];
            int tp = d < 0 ? -d : d;
            uint32_t nib = 0;
            if (tp == tmax) {
                if (d >= 1)
                    nib = (uint32_t)b13[o] | ((uint32_t)b24[o] << 2);
                else if (d <= -1)
                    nib = ((uint32_t)b24[o] << 4) | ((uint32_t)b13[o] << 6);
            }
            word |= nib << (8 * o);
        }
        const size_t pix = ((size_t)b * HH + (y0 + yy)) * WW + (x0 + tx);
        g_border[pix] = word;
        out[pix] = 0.0f;   // zero-init for stage2's atomic accumulation
    }
}

// ---------------------------------------------------------------------------
// Stage 2: depthwise 23x23 conv + spike combination. ONE (tile, group) per
// block; results combine via predicated atomicAdd. Block (32,2), tile 32x32,
// 16 output rows/thread with a 16-register rolling window; channel pair in
// one FFMA2. The 23 weights of the current dx-column are PRELOADED into
// registers before the dy loop, removing the LDS->FFMA2 latency exposure
// that capped the fma pipe at ~70%.
// ---------------------------------------------------------------------------
__global__ __launch_bounds__(64)
void stage2_kernel(const float* __restrict__ Wg, float* __restrict__ out)
{
    __shared__ ull sh[54][55];    // decoded (chanA, chanB) pairs (23.8 KB)
    __shared__ ull wsh[529];      // duplicated weights (4.2 KB)

    const int zz  = blockIdx.z;          // 0..31 = b*8 + grp
    const int b   = zz >> 3;
    const int grp = zz & 7;
    const int x0 = blockIdx.x * 32;
    const int y0 = blockIdx.y * 32;
    const int tx = threadIdx.x;   // 0..31
    const int ty = threadIdx.y;   // 0..1
    const int tid = ty * 32 + tx;
    const int yb = ty * 16;

    const uint32_t* __restrict__ bor = g_border + (size_t)b * HH * WW;
    const int shift = grp * 4;

    for (int i = tid; i < 529; i += 64) {
        float w = Wg[grp * 2 * 529 + i];
        wsh[i] = pack2(w, w);
    }

    for (int ry = ty; ry < 54; ry += 2) {
        int gy = y0 - 11 + ry;
        for (int rx = tx; rx < 54; rx += 32) {
            int gx = x0 - 11 + rx;
            uint32_t v = 0;
            if (((unsigned)gy < HH) && ((unsigned)gx < WW)) v = bor[gy * WW + gx];
            sh[ry][rx] = pack2((float)((v >> shift) & 3u),
                               (float)((v >> (shift + 2)) & 3u));
        }
    }
    __syncthreads();

    ull a[16];
    #pragma unroll
    for (int o = 0; o < 16; ++o) a[o] = 0ull;

    #pragma unroll 1
    for (int dx = 0; dx < 23; ++dx) {
        const int c = tx + dx;

        // Preload this dx-column's 23 weights into registers (broadcast LDS,
        // issued back-to-back; first consumer is >=29 cyc downstream).
        ull w[23];
        #pragma unroll
        for (int k = 0; k < 23; ++k) w[k] = wsh[k * 23 + dx];

        ull r[16];
        #pragma unroll
        for (int o = 0; o < 16; ++o) r[o] = sh[yb + o][c];

        #pragma unroll
        for (int dy = 0; dy < 23; ++dy) {
            #pragma unroll
            for (int o = 0; o < 16; ++o) a[o] = ffma2(w[dy], r[o], a[o]);
            if (dy < 22) {
                #pragma unroll
                for (int o = 0; o < 15; ++o) r[o] = r[o + 1];
                r[15] = sh[yb + dy + 16][c];
            }
        }
    }

    #pragma unroll
    for (int o = 0; o < 16; ++o) {
        float2 v = unpack2(a[o]);
        if (v.x >= 1.0f && v.y < 1.0f)
            atomicAdd(&out[((size_t)b * HH + (y0 + yb + o)) * WW + x0 + tx], 1.0f);
    }
}

// ---------------------------------------------------------------------------
extern "C" void kernel_launch(void* const* d_in, const int* in_sizes, int n_in,
                              void* d_out, int out_size)
{
    const float* inp = nullptr;
    const float* Wb  = nullptr;
    const float* Wg  = nullptr;
    for (int i = 0; i < n_in; ++i) {
        if (in_sizes[i] == NB * 2 * HH * WW) inp = (const float*)d_in[i];
        else if (in_sizes[i] == 8 * 121)     Wb  = (const float*)d_in[i];
        else if (in_sizes[i] == 16 * 529)    Wg  = (const float*)d_in[i];
    }

    dim3 grid1(WW / 32, HH / 32, NB);
    dim3 blk1(32, 16);
    stage1_kernel<<<grid1, blk1>>>(inp, Wb, (float*)d_out);

    dim3 grid2(WW / 32, HH / 32, NB * 8);   // one (tile, group) per block
    dim3 blk2(32, 2);
    stage2_kernel<<<grid2, blk2>>>(Wg, (float*)d_out);
}

// round 7
// speedup vs baseline: 1.6867x; 1.6867x over previous
#include <cuda_runtime.h>
#include <stdint.h>

#define HH 512
#define WW 512
#define NB 4

typedef unsigned long long ull;

// Packed border tensor: 16 channels x 2 bits per pixel (values in {0,1,2}).
__device__ uint32_t g_border[NB * HH * WW];

__device__ __forceinline__ ull ffma2(ull a, ull b, ull c) {
    ull d;
    asm("fma.rn.f32x2 %0, %1, %2, %3;" : "=l"(d) : "l"(a), "l"(b), "l"(c));
    return d;
}
__device__ __forceinline__ ull pack2(float x, float y) {
    ull d;
    asm("mov.b64 %0, {%1, %2};" : "=l"(d) : "f"(x), "f"(y));
    return d;
}
__device__ __forceinline__ float2 unpack2(ull v) {
    float2 r;
    asm("mov.b64 {%0, %1}, %2;" : "=f"(r.x), "=f"(r.y) : "l"(v));
    return r;
}

// ---------------------------------------------------------------------------
// Stage 1: 11x11 conv (1->8 ch) on both input planes + spike/WTA logic.
// Planes (in0,in1) ride in one FFMA2. Duplicated weights stored [tap][filter]
// so each tap's 8 weights come from 4 broadcast LDS.128.
// Block (32,16), tile 32x32. Also zeroes d_out (stage2 accumulates via atomics).
// ---------------------------------------------------------------------------
__global__ __launch_bounds__(512)
void stage1_kernel(const float* __restrict__ inp, const float* __restrict__ Wb,
                   float* __restrict__ out)
{
    __shared__ ull s01[42][44];                  // (in0,in1) packed (14.8 KB)
    __shared__ __align__(16) ull dsh[121 * 8];   // dup weights [t][f] (7.7 KB)

    const int b  = blockIdx.z;
    const int x0 = blockIdx.x * 32;
    const int y0 = blockIdx.y * 32;
    const int tx = threadIdx.x;      // 0..31
    const int ty = threadIdx.y;      // 0..15
    const int tid = ty * 32 + tx;

    for (int i = tid; i < 968; i += 512) {
        int t = i >> 3, f = i & 7;
        float w = Wb[f * 121 + t];
        dsh[i] = pack2(w, w);
    }

    const float* __restrict__ in0 = inp + ((size_t)b * 2 + 0) * HH * WW;
    const float* __restrict__ in1 = inp + ((size_t)b * 2 + 1) * HH * WW;

    for (int ry = ty; ry < 42; ry += 16) {
        int gy = y0 - 5 + ry;
        for (int rx = tx; rx < 42; rx += 32) {
            int gx = x0 - 5 + rx;
            bool ok = ((unsigned)gy < HH) && ((unsigned)gx < WW);
            float v0 = ok ? in0[gy * WW + gx] : 0.0f;
            float v1 = ok ? in1[gy * WW + gx] : 0.0f;
            s01[ry][rx] = pack2(v0, v1);
        }
    }
    __syncthreads();

    ull acc0[8], acc1[8];            // .x = pos conv, .y = neg conv
    #pragma unroll
    for (int f = 0; f < 8; ++f) { acc0[f] = 0ull; acc1[f] = 0ull; }

    #pragma unroll 1
    for (int dy = 0; dy < 11; ++dy) {
        #pragma unroll
        for (int dx = 0; dx < 11; ++dx) {
            ull xa = s01[ty + dy][tx + dx];
            ull xb = s01[ty + 16 + dy][tx + dx];
            const int t = dy * 11 + dx;
            const ulonglong2* wp = (const ulonglong2*)&dsh[t * 8];
            #pragma unroll
            for (int fp = 0; fp < 4; ++fp) {
                ulonglong2 w2 = wp[fp];
                acc0[2*fp]   = ffma2(w2.x, xa, acc0[2*fp]);
                acc1[2*fp]   = ffma2(w2.x, xb, acc1[2*fp]);
                acc0[2*fp+1] = ffma2(w2.y, xa, acc0[2*fp+1]);
                acc1[2*fp+1] = ffma2(w2.y, xb, acc1[2*fp+1]);
            }
        }
    }

    #pragma unroll
    for (int k = 0; k < 2; ++k) {
        const int yy = ty + k * 16;
        float2 ctr = unpack2(s01[yy + 5][tx + 5]);
        float vm = ctr.x + ctr.y;

        int b13[4], b24[4];
        #pragma unroll
        for (int o = 0; o < 4; ++o) {
            float2 e = unpack2(k == 0 ? acc0[2*o]   : acc1[2*o]);
            float2 d = unpack2(k == 0 ? acc0[2*o+1] : acc1[2*o+1]);
            float pe = e.x >= 1.0f ? 1.0f : 0.0f;
            float ne = e.y >= 1.0f ? 1.0f : 0.0f;
            float po = d.x >= 1.0f ? 1.0f : 0.0f;
            float no = d.y >= 1.0f ? 1.0f : 0.0f;
            int s1 = (vm * (pe - 1.5f * no) >= 1.0f) ? 1 : 0;
            int s2 = (vm * (ne - 1.5f * po) >= 1.0f) ? 1 : 0;
            int s3 = (vm * (po - 1.5f * ne) >= 1.0f) ? 1 : 0;
            int s4 = (vm * (no - 1.5f * pe) >= 1.0f) ? 1 : 0;
            b13[o] = s1 + s2;
            b24[o] = s3 + s4;
        }

        int tmax = 0;
        #pragma unroll
        for (int o = 0; o < 4; ++o) {
            int d = b13[o] - b24[o];
            int tp = d < 0 ? -d : d;
            if (tp > tmax) tmax = tp;
        }

        uint32_t word = 0;
        #pragma unroll
        for (int o = 0; o < 4; ++o) {
            int d = b13[o] - b24[o];
            int tp = d < 0 ? -d : d;
            uint32_t nib = 0;
            if (tp == tmax) {
                if (d >= 1)
                    nib = (uint32_t)b13[o] | ((uint32_t)b24[o] << 2);
                else if (d <= -1)
                    nib = ((uint32_t)b24[o] << 4) | ((uint32_t)b13[o] << 6);
            }
            word |= nib << (8 * o);
        }
        const size_t pix = ((size_t)b * HH + (y0 + yy)) * WW + (x0 + tx);
        g_border[pix] = word;
        out[pix] = 0.0f;   // zero-init for stage2's atomic accumulation
    }
}

// ---------------------------------------------------------------------------
// Stage 2: depthwise 23x23 conv + spike combination. ONE (tile, group) per
// block; results combine via predicated atomicAdd. Block (32,4), tile 32x64
// (taller tile: halo loads per output 2.85 -> 2.27), 16 output rows/thread
// with the proven R4 rolling 16-register window + depth-1 weight prefetch.
// ---------------------------------------------------------------------------
__global__ __launch_bounds__(128)
void stage2_kernel(const float* __restrict__ Wg, float* __restrict__ out)
{
    __shared__ ull sh[86][55];    // decoded (chanA, chanB) pairs (37.8 KB)
    __shared__ ull wsh[529];      // duplicated weights (4.2 KB)

    const int zz  = blockIdx.z;          // 0..31 = b*8 + grp
    const int b   = zz >> 3;
    const int grp = zz & 7;
    const int x0 = blockIdx.x * 32;
    const int y0 = blockIdx.y * 64;
    const int tx = threadIdx.x;   // 0..31
    const int ty = threadIdx.y;   // 0..3
    const int tid = ty * 32 + tx;
    const int yb = ty * 16;

    const uint32_t* __restrict__ bor = g_border + (size_t)b * HH * WW;
    const int shift = grp * 4;

    for (int i = tid; i < 529; i += 128) {
        float w = Wg[grp * 2 * 529 + i];
        wsh[i] = pack2(w, w);
    }

    for (int ry = ty; ry < 86; ry += 4) {
        int gy = y0 - 11 + ry;
        for (int rx = tx; rx < 54; rx += 32) {
            int gx = x0 - 11 + rx;
            uint32_t v = 0;
            if (((unsigned)gy < HH) && ((unsigned)gx < WW)) v = bor[gy * WW + gx];
            sh[ry][rx] = pack2((float)((v >> shift) & 3u),
                               (float)((v >> (shift + 2)) & 3u));
        }
    }
    __syncthreads();

    ull a[16];
    #pragma unroll
    for (int o = 0; o < 16; ++o) a[o] = 0ull;

    #pragma unroll 1
    for (int dx = 0; dx < 23; ++dx) {
        const int c = tx + dx;

        ull r[16];
        #pragma unroll
        for (int o = 0; o < 16; ++o) r[o] = sh[yb + o][c];

        ull w0 = wsh[dx];   // weight for dy=0
        #pragma unroll
        for (int dy = 0; dy < 23; ++dy) {
            // Depth-1 prefetch: next weight issued before this step's FMAs.
            ull wn = (dy < 22) ? wsh[(dy + 1) * 23 + dx] : 0ull;
            #pragma unroll
            for (int o = 0; o < 16; ++o) a[o] = ffma2(w0, r[o], a[o]);
            if (dy < 22) {
                #pragma unroll
                for (int o = 0; o < 15; ++o) r[o] = r[o + 1];
                r[15] = sh[yb + dy + 16][c];
            }
            w0 = wn;
        }
    }

    #pragma unroll
    for (int o = 0; o < 16; ++o) {
        float2 v = unpack2(a[o]);
        if (v.x >= 1.0f && v.y < 1.0f)
            atomicAdd(&out[((size_t)b * HH + (y0 + yb + o)) * WW + x0 + tx], 1.0f);
    }
}

// ---------------------------------------------------------------------------
extern "C" void kernel_launch(void* const* d_in, const int* in_sizes, int n_in,
                              void* d_out, int out_size)
{
    const float* inp = nullptr;
    const float* Wb  = nullptr;
    const float* Wg  = nullptr;
    for (int i = 0; i < n_in; ++i) {
        if (in_sizes[i] == NB * 2 * HH * WW) inp = (const float*)d_in[i];
        else if (in_sizes[i] == 8 * 121)     Wb  = (const float*)d_in[i];
        else if (in_sizes[i] == 16 * 529)    Wg  = (const float*)d_in[i];
    }

    dim3 grid1(WW / 32, HH / 32, NB);
    dim3 blk1(32, 16);
    stage1_kernel<<<grid1, blk1>>>(inp, Wb, (float*)d_out);

    dim3 grid2(WW / 32, HH / 64, NB * 8);   // one (32x64 tile, group) per block
    dim3 blk2(32, 4);
    stage2_kernel<<<grid2, blk2>>>(Wg, (float*)d_out);
}

// round 9
// speedup vs baseline: 4.5108x; 2.6744x over previous
#include <cuda_runtime.h>
#include <stdint.h>

#define HH 512
#define WW 512
#define NB 4

typedef unsigned long long ull;

// Packed border tensor: 16 channels x 2 bits per pixel (values in {0,1,2}).
__device__ uint32_t g_border[NB * HH * WW];

__device__ __forceinline__ ull ffma2(ull a, ull b, ull c) {
    ull d;
    asm("fma.rn.f32x2 %0, %1, %2, %3;" : "=l"(d) : "l"(a), "l"(b), "l"(c));
    return d;
}
__device__ __forceinline__ ull pack2(float x, float y) {
    ull d;
    asm("mov.b64 %0, {%1, %2};" : "=l"(d) : "f"(x), "f"(y));
    return d;
}
__device__ __forceinline__ float2 unpack2(ull v) {
    float2 r;
    asm("mov.b64 {%0, %1}, %2;" : "=f"(r.x), "=f"(r.y) : "l"(v));
    return r;
}

// ---------------------------------------------------------------------------
// Stage 1: 11x11 conv (1->8 ch) on both input planes + spike/WTA logic.
// Planes (in0,in1) ride in one FFMA2. Weights [tap][filter] -> 4 broadcast
// LDS.128 per tap. Block (32,8), tile 32x32, 4 rows/thread: per tap 8 LSU-cyc
// feed 16 fma-cyc -> fma-bound. Also zeroes this batch's d_out plane.
// ---------------------------------------------------------------------------
__global__ __launch_bounds__(256, 2)
void stage1_kernel(const float* __restrict__ inp, const float* __restrict__ Wb,
                   float* __restrict__ out)
{
    __shared__ ull s01[42][44];                  // (in0,in1) packed (14.8 KB)
    __shared__ __align__(16) ull dsh[121 * 8];   // dup weights [t][f] (7.7 KB)

    const int b  = blockIdx.z;
    const int x0 = blockIdx.x * 32;
    const int y0 = blockIdx.y * 32;
    const int tx = threadIdx.x;      // 0..31
    const int ty = threadIdx.y;      // 0..7
    const int tid = ty * 32 + tx;

    for (int i = tid; i < 968; i += 256) {
        int t = i >> 3, f = i & 7;
        float w = Wb[f * 121 + t];
        dsh[i] = pack2(w, w);
    }

    const float* __restrict__ in0 = inp + ((size_t)b * 2 + 0) * HH * WW;
    const float* __restrict__ in1 = inp + ((size_t)b * 2 + 1) * HH * WW;

    for (int ry = ty; ry < 42; ry += 8) {
        int gy = y0 - 5 + ry;
        for (int rx = tx; rx < 42; rx += 32) {
            int gx = x0 - 5 + rx;
            bool ok = ((unsigned)gy < HH) && ((unsigned)gx < WW);
            float v0 = ok ? in0[gy * WW + gx] : 0.0f;
            float v1 = ok ? in1[gy * WW + gx] : 0.0f;
            s01[ry][rx] = pack2(v0, v1);
        }
    }
    __syncthreads();

    ull acc[4][8];                   // [row k][filter], .x=pos conv .y=neg conv
    #pragma unroll
    for (int k = 0; k < 4; ++k)
        #pragma unroll
        for (int f = 0; f < 8; ++f) acc[k][f] = 0ull;

    #pragma unroll 1
    for (int dy = 0; dy < 11; ++dy) {
        #pragma unroll
        for (int dx = 0; dx < 11; ++dx) {
            ull x0v = s01[ty      + dy][tx + dx];
            ull x1v = s01[ty +  8 + dy][tx + dx];
            ull x2v = s01[ty + 16 + dy][tx + dx];
            ull x3v = s01[ty + 24 + dy][tx + dx];
            const int t = dy * 11 + dx;
            const ulonglong2* wp = (const ulonglong2*)&dsh[t * 8];
            #pragma unroll
            for (int fp = 0; fp < 4; ++fp) {
                ulonglong2 w2 = wp[fp];
                acc[0][2*fp]   = ffma2(w2.x, x0v, acc[0][2*fp]);
                acc[1][2*fp]   = ffma2(w2.x, x1v, acc[1][2*fp]);
                acc[2][2*fp]   = ffma2(w2.x, x2v, acc[2][2*fp]);
                acc[3][2*fp]   = ffma2(w2.x, x3v, acc[3][2*fp]);
                acc[0][2*fp+1] = ffma2(w2.y, x0v, acc[0][2*fp+1]);
                acc[1][2*fp+1] = ffma2(w2.y, x1v, acc[1][2*fp+1]);
                acc[2][2*fp+1] = ffma2(w2.y, x2v, acc[2][2*fp+1]);
                acc[3][2*fp+1] = ffma2(w2.y, x3v, acc[3][2*fp+1]);
            }
        }
    }

    #pragma unroll
    for (int k = 0; k < 4; ++k) {
        const int yy = ty + k * 8;
        float2 ctr = unpack2(s01[yy + 5][tx + 5]);
        float vm = ctr.x + ctr.y;

        int b13[4], b24[4];
        #pragma unroll
        for (int o = 0; o < 4; ++o) {
            float2 e = unpack2(acc[k][2*o]);
            float2 d = unpack2(acc[k][2*o+1]);
            float pe = e.x >= 1.0f ? 1.0f : 0.0f;
            float ne = e.y >= 1.0f ? 1.0f : 0.0f;
            float po = d.x >= 1.0f ? 1.0f : 0.0f;
            float no = d.y >= 1.0f ? 1.0f : 0.0f;
            int s1 = (vm * (pe - 1.5f * no) >= 1.0f) ? 1 : 0;
            int s2 = (vm * (ne - 1.5f * po) >= 1.0f) ? 1 : 0;
            int s3 = (vm * (po - 1.5f * ne) >= 1.0f) ? 1 : 0;
            int s4 = (vm * (no - 1.5f * pe) >= 1.0f) ? 1 : 0;
            b13[o] = s1 + s2;
            b24[o] = s3 + s4;
        }

        int tmax = 0;
        #pragma unroll
        for (int o = 0; o < 4; ++o) {
            int d = b13[o] - b24[o];
            int tp = d < 0 ? -d : d;
            if (tp > tmax) tmax = tp;
        }

        uint32_t word = 0;
        #pragma unroll
        for (int o = 0; o < 4; ++o) {
            int d = b13[o] - b24[o];
            int tp = d < 0 ? -d : d;
            uint32_t nib = 0;
            if (tp == tmax) {
                if (d >= 1)
                    nib = (uint32_t)b13[o] | ((uint32_t)b24[o] << 2);
                else if (d <= -1)
                    nib = ((uint32_t)b24[o] << 4) | ((uint32_t)b13[o] << 6);
            }
            word |= nib << (8 * o);
        }
        const size_t pix = ((size_t)b * HH + (y0 + yy)) * WW + (x0 + tx);
        g_border[pix] = word;
        out[pix] = 0.0f;   // zero-init for stage2's atomic accumulation
    }
}

// ---------------------------------------------------------------------------
// Stage 2: depthwise 23x23 conv + spike combination. ONE (tile, group) per
// block; results combine via predicated atomicAdd. Block (32,4), tile 32x64,
// 16 output rows/thread, rolling 16-register window + depth-1 weight
// prefetch. NEW: if this group's nibble is zero across the whole halo
// (WTA gating makes losing orientations all-zero), the conv is identically
// zero -> spikes are 0 -> early-exit (output already zeroed by stage1).
// ---------------------------------------------------------------------------
__global__ __launch_bounds__(128)
void stage2_kernel(const float* __restrict__ Wg, float* __restrict__ out)
{
    __shared__ ull sh[86][55];    // decoded (chanA, chanB) pairs (37.8 KB)
    __shared__ ull wsh[529];      // duplicated weights (4.2 KB)

    const int zz  = blockIdx.z;          // 0..31 = b*8 + grp
    const int b   = zz >> 3;
    const int grp = zz & 7;
    const int x0 = blockIdx.x * 32;
    const int y0 = blockIdx.y * 64;
    const int tx = threadIdx.x;   // 0..31
    const int ty = threadIdx.y;   // 0..3
    const int tid = ty * 32 + tx;
    const int yb = ty * 16;

    const uint32_t* __restrict__ bor = g_border + (size_t)b * HH * WW;
    const int shift = grp * 4;

    for (int i = tid; i < 529; i += 128) {
        float w = Wg[grp * 2 * 529 + i];
        wsh[i] = pack2(w, w);
    }

    uint32_t orw = 0;
    for (int ry = ty; ry < 86; ry += 4) {
        int gy = y0 - 11 + ry;
        for (int rx = tx; rx < 54; rx += 32) {
            int gx = x0 - 11 + rx;
            uint32_t v = 0;
            if (((unsigned)gy < HH) && ((unsigned)gx < WW)) v = bor[gy * WW + gx];
            orw |= v;
            sh[ry][rx] = pack2((float)((v >> shift) & 3u),
                               (float)((v >> (shift + 2)) & 3u));
        }
    }
    // Block-wide: does this group have ANY nonzero value in the halo?
    int any = __syncthreads_or((int)((orw >> shift) & 0xFu));
    if (!any) return;   // conv == 0 everywhere -> spikes 0 -> nothing to add

    ull a[16];
    #pragma unroll
    for (int o = 0; o < 16; ++o) a[o] = 0ull;

    #pragma unroll 1
    for (int dx = 0; dx < 23; ++dx) {
        const int c = tx + dx;

        ull r[16];
        #pragma unroll
        for (int o = 0; o < 16; ++o) r[o] = sh[yb + o][c];

        ull w0 = wsh[dx];   // weight for dy=0
        #pragma unroll
        for (int dy = 0; dy < 23; ++dy) {
            ull wn = (dy < 22) ? wsh[(dy + 1) * 23 + dx] : 0ull;
            #pragma unroll
            for (int o = 0; o < 16; ++o) a[o] = ffma2(w0, r[o], a[o]);
            if (dy < 22) {
                #pragma unroll
                for (int o = 0; o < 15; ++o) r[o] = r[o + 1];
                r[15] = sh[yb + dy + 16][c];
            }
            w0 = wn;
        }
    }

    #pragma unroll
    for (int o = 0; o < 16; ++o) {
        float2 v = unpack2(a[o]);
        if (v.x >= 1.0f && v.y < 1.0f)
            atomicAdd(&out[((size_t)b * HH + (y0 + yb + o)) * WW + x0 + tx], 1.0f);
    }
}

// ---------------------------------------------------------------------------
extern "C" void kernel_launch(void* const* d_in, const int* in_sizes, int n_in,
                              void* d_out, int out_size)
{
    const float* inp = nullptr;
    const float* Wb  = nullptr;
    const float* Wg  = nullptr;
    for (int i = 0; i < n_in; ++i) {
        if (in_sizes[i] == NB * 2 * HH * WW) inp = (const float*)d_in[i];
        else if (in_sizes[i] == 8 * 121)     Wb  = (const float*)d_in[i];
        else if (in_sizes[i] == 16 * 529)    Wg  = (const float*)d_in[i];
    }

    dim3 grid1(WW / 32, HH / 32, NB);
    dim3 blk1(32, 8);
    stage1_kernel<<<grid1, blk1>>>(inp, Wb, (float*)d_out);

    dim3 grid2(WW / 32, HH / 64, NB * 8);   // one (32x64 tile, group) per block
    dim3 blk2(32, 4);
    stage2_kernel<<<grid2, blk2>>>(Wg, (float*)d_out);
}

// round 10
// speedup vs baseline: 7.0809x; 1.5698x over previous
#include <cuda_runtime.h>
#include <stdint.h>

#define HH 512
#define WW 512
#define NB 4

typedef unsigned long long ull;

// Packed border tensor: 16 channels x 2 bits per pixel (values in {0,1,2}).
__device__ uint32_t g_border[NB * HH * WW];
// Per-(batch, 32x32 tile) OR of all border words: 16x16 tiles per batch.
__device__ uint32_t g_tilemask[NB * 16 * 16];

__device__ __forceinline__ ull ffma2(ull a, ull b, ull c) {
    ull d;
    asm("fma.rn.f32x2 %0, %1, %2, %3;" : "=l"(d) : "l"(a), "l"(b), "l"(c));
    return d;
}
__device__ __forceinline__ ull pack2(float x, float y) {
    ull d;
    asm("mov.b64 %0, {%1, %2};" : "=l"(d) : "f"(x), "f"(y));
    return d;
}
__device__ __forceinline__ float2 unpack2(ull v) {
    float2 r;
    asm("mov.b64 {%0, %1}, %2;" : "=f"(r.x), "=f"(r.y) : "l"(v));
    return r;
}

// ---------------------------------------------------------------------------
// Stage 1: 11x11 conv (1->8 ch) on both input planes + spike/WTA logic.
// Block (32,8), tile 32x32, 4 rows/thread. Also zeroes this batch's d_out
// plane and publishes the tile's OR-mask for stage2's early skip.
// ---------------------------------------------------------------------------
__global__ __launch_bounds__(256, 2)
void stage1_kernel(const float* __restrict__ inp, const float* __restrict__ Wb,
                   float* __restrict__ out)
{
    __shared__ ull s01[42][44];                  // (in0,in1) packed (14.8 KB)
    __shared__ __align__(16) ull dsh[121 * 8];   // dup weights [t][f] (7.7 KB)

    const int b  = blockIdx.z;
    const int x0 = blockIdx.x * 32;
    const int y0 = blockIdx.y * 32;
    const int tx = threadIdx.x;      // 0..31
    const int ty = threadIdx.y;      // 0..7
    const int tid = ty * 32 + tx;

    for (int i = tid; i < 968; i += 256) {
        int t = i >> 3, f = i & 7;
        float w = Wb[f * 121 + t];
        dsh[i] = pack2(w, w);
    }

    const float* __restrict__ in0 = inp + ((size_t)b * 2 + 0) * HH * WW;
    const float* __restrict__ in1 = inp + ((size_t)b * 2 + 1) * HH * WW;

    for (int ry = ty; ry < 42; ry += 8) {
        int gy = y0 - 5 + ry;
        for (int rx = tx; rx < 42; rx += 32) {
            int gx = x0 - 5 + rx;
            bool ok = ((unsigned)gy < HH) && ((unsigned)gx < WW);
            float v0 = ok ? in0[gy * WW + gx] : 0.0f;
            float v1 = ok ? in1[gy * WW + gx] : 0.0f;
            s01[ry][rx] = pack2(v0, v1);
        }
    }
    __syncthreads();

    ull acc[4][8];                   // [row k][filter], .x=pos conv .y=neg conv
    #pragma unroll
    for (int k = 0; k < 4; ++k)
        #pragma unroll
        for (int f = 0; f < 8; ++f) acc[k][f] = 0ull;

    #pragma unroll 1
    for (int dy = 0; dy < 11; ++dy) {
        #pragma unroll
        for (int dx = 0; dx < 11; ++dx) {
            ull x0v = s01[ty      + dy][tx + dx];
            ull x1v = s01[ty +  8 + dy][tx + dx];
            ull x2v = s01[ty + 16 + dy][tx + dx];
            ull x3v = s01[ty + 24 + dy][tx + dx];
            const int t = dy * 11 + dx;
            const ulonglong2* wp = (const ulonglong2*)&dsh[t * 8];
            #pragma unroll
            for (int fp = 0; fp < 4; ++fp) {
                ulonglong2 w2 = wp[fp];
                acc[0][2*fp]   = ffma2(w2.x, x0v, acc[0][2*fp]);
                acc[1][2*fp]   = ffma2(w2.x, x1v, acc[1][2*fp]);
                acc[2][2*fp]   = ffma2(w2.x, x2v, acc[2][2*fp]);
                acc[3][2*fp]   = ffma2(w2.x, x3v, acc[3][2*fp]);
                acc[0][2*fp+1] = ffma2(w2.y, x0v, acc[0][2*fp+1]);
                acc[1][2*fp+1] = ffma2(w2.y, x1v, acc[1][2*fp+1]);
                acc[2][2*fp+1] = ffma2(w2.y, x2v, acc[2][2*fp+1]);
                acc[3][2*fp+1] = ffma2(w2.y, x3v, acc[3][2*fp+1]);
            }
        }
    }

    uint32_t myor = 0;
    #pragma unroll
    for (int k = 0; k < 4; ++k) {
        const int yy = ty + k * 8;
        float2 ctr = unpack2(s01[yy + 5][tx + 5]);
        float vm = ctr.x + ctr.y;

        int b13[4], b24[4];
        #pragma unroll
        for (int o = 0; o < 4; ++o) {
            float2 e = unpack2(acc[k][2*o]);
            float2 d = unpack2(acc[k][2*o+1]);
            float pe = e.x >= 1.0f ? 1.0f : 0.0f;
            float ne = e.y >= 1.0f ? 1.0f : 0.0f;
            float po = d.x >= 1.0f ? 1.0f : 0.0f;
            float no = d.y >= 1.0f ? 1.0f : 0.0f;
            int s1 = (vm * (pe - 1.5f * no) >= 1.0f) ? 1 : 0;
            int s2 = (vm * (ne - 1.5f * po) >= 1.0f) ? 1 : 0;
            int s3 = (vm * (po - 1.5f * ne) >= 1.0f) ? 1 : 0;
            int s4 = (vm * (no - 1.5f * pe) >= 1.0f) ? 1 : 0;
            b13[o] = s1 + s2;
            b24[o] = s3 + s4;
        }

        int tmax = 0;
        #pragma unroll
        for (int o = 0; o < 4; ++o) {
            int d = b13[o] - b24[o];
            int tp = d < 0 ? -d : d;
            if (tp > tmax) tmax = tp;
        }

        uint32_t word = 0;
        #pragma unroll
        for (int o = 0; o < 4; ++o) {
            int d = b13[o] - b24[o];
            int tp = d < 0 ? -d : d;
            uint32_t nib = 0;
            if (tp == tmax) {
                if (d >= 1)
                    nib = (uint32_t)b13[o] | ((uint32_t)b24[o] << 2);
                else if (d <= -1)
                    nib = ((uint32_t)b24[o] << 4) | ((uint32_t)b13[o] << 6);
            }
            word |= nib << (8 * o);
        }
        const size_t pix = ((size_t)b * HH + (y0 + yy)) * WW + (x0 + tx);
        g_border[pix] = word;
        out[pix] = 0.0f;   // zero-init for stage2's atomic accumulation
        myor |= word;
    }

    // Publish this 32x32 tile's OR so stage2 can skip before loading anything.
    uint32_t tileor = (uint32_t)__syncthreads_or((int)myor);
    if (tid == 0)
        g_tilemask[b * 256 + blockIdx.y * 16 + blockIdx.x] = tileor;
}

// ---------------------------------------------------------------------------
// Stage 2: depthwise 23x23 conv + spike combination. ONE (tile, group) per
// block. EARLY SKIP: probe <=12 tile-mask words covering the halo; if this
// group's nibble is zero there, exit before loading weights or halo.
// Block (32,4), tile 32x64, 16 output rows/thread, rolling window +
// depth-1 weight prefetch. Results combine via predicated atomicAdd.
// ---------------------------------------------------------------------------
__global__ __launch_bounds__(128)
void stage2_kernel(const float* __restrict__ Wg, float* __restrict__ out)
{
    __shared__ ull sh[86][55];    // decoded (chanA, chanB) pairs (37.8 KB)
    __shared__ ull wsh[529];      // duplicated weights (4.2 KB)

    const int zz  = blockIdx.z;          // 0..31 = b*8 + grp
    const int b   = zz >> 3;
    const int grp = zz & 7;
    const int x0 = blockIdx.x * 32;
    const int y0 = blockIdx.y * 64;
    const int tx = threadIdx.x;   // 0..31
    const int ty = threadIdx.y;   // 0..3
    const int tid = ty * 32 + tx;
    const int yb = ty * 16;
    const int shift = grp * 4;

    // ---- mask probe: OR the <=12 tile-masks intersecting the halo ----
    {
        const int txl = (x0 >= 11 ? x0 - 11 : 0) >> 5;
        const int txh = ((x0 + 42 < WW ? x0 + 42 : WW - 1)) >> 5;
        const int tyl = (y0 >= 11 ? y0 - 11 : 0) >> 5;
        const int tyh = ((y0 + 74 < HH ? y0 + 74 : HH - 1)) >> 5;
        const int nx = txh - txl + 1;            // <=3
        const int nt = nx * (tyh - tyl + 1);     // <=12
        uint32_t m = 0;
        if (tid < nt) {
            int tyi = tyl + tid / nx;
            int txi = txl + tid % nx;
            m = g_tilemask[b * 256 + tyi * 16 + txi];
        }
        int any = __syncthreads_or((int)((m >> shift) & 0xFu));
        if (!any) return;   // group empty over whole halo -> output untouched
    }

    const uint32_t* __restrict__ bor = g_border + (size_t)b * HH * WW;

    for (int i = tid; i < 529; i += 128) {
        float w = Wg[grp * 2 * 529 + i];
        wsh[i] = pack2(w, w);
    }

    for (int ry = ty; ry < 86; ry += 4) {
        int gy = y0 - 11 + ry;
        for (int rx = tx; rx < 54; rx += 32) {
            int gx = x0 - 11 + rx;
            uint32_t v = 0;
            if (((unsigned)gy < HH) && ((unsigned)gx < WW)) v = bor[gy * WW + gx];
            sh[ry][rx] = pack2((float)((v >> shift) & 3u),
                               (float)((v >> (shift + 2)) & 3u));
        }
    }
    __syncthreads();

    ull a[16];
    #pragma unroll
    for (int o = 0; o < 16; ++o) a[o] = 0ull;

    #pragma unroll 1
    for (int dx = 0; dx < 23; ++dx) {
        const int c = tx + dx;

        ull r[16];
        #pragma unroll
        for (int o = 0; o < 16; ++o) r[o] = sh[yb + o][c];

        ull w0 = wsh[dx];   // weight for dy=0
        #pragma unroll
        for (int dy = 0; dy < 23; ++dy) {
            ull wn = (dy < 22) ? wsh[(dy + 1) * 23 + dx] : 0ull;
            #pragma unroll
            for (int o = 0; o < 16; ++o) a[o] = ffma2(w0, r[o], a[o]);
            if (dy < 22) {
                #pragma unroll
                for (int o = 0; o < 15; ++o) r[o] = r[o + 1];
                r[15] = sh[yb + dy + 16][c];
            }
            w0 = wn;
        }
    }

    #pragma unroll
    for (int o = 0; o < 16; ++o) {
        float2 v = unpack2(a[o]);
        if (v.x >= 1.0f && v.y < 1.0f)
            atomicAdd(&out[((size_t)b * HH + (y0 + yb + o)) * WW + x0 + tx], 1.0f);
    }
}

// ---------------------------------------------------------------------------
extern "C" void kernel_launch(void* const* d_in, const int* in_sizes, int n_in,
                              void* d_out, int out_size)
{
    const float* inp = nullptr;
    const float* Wb  = nullptr;
    const float* Wg  = nullptr;
    for (int i = 0; i < n_in; ++i) {
        if (in_sizes[i] == NB * 2 * HH * WW) inp = (const float*)d_in[i];
        else if (in_sizes[i] == 8 * 121)     Wb  = (const float*)d_in[i];
        else if (in_sizes[i] == 16 * 529)    Wg  = (const float*)d_in[i];
    }

    dim3 grid1(WW / 32, HH / 32, NB);
    dim3 blk1(32, 8);
    stage1_kernel<<<grid1, blk1>>>(inp, Wb, (float*)d_out);

    dim3 grid2(WW / 32, HH / 64, NB * 8);   // one (32x64 tile, group) per block
    dim3 blk2(32, 4);
    stage2_kernel<<<grid2, blk2>>>(Wg, (float*)d_out);
}

// round 11
// speedup vs baseline: 7.5093x; 1.0605x over previous
#include <cuda_runtime.h>
#include <stdint.h>

#define HH 512
#define WW 512
#define NB 4

typedef unsigned long long ull;

// Packed border tensor: 16 channels x 2 bits per pixel (values in {0,1,2}).
__device__ uint32_t g_border[NB * HH * WW];
// Per-(batch, 32x16 tile) OR of all border words: 16 x 32 tiles per batch.
__device__ uint32_t g_tilemask[NB * 16 * 32];

__device__ __forceinline__ ull ffma2(ull a, ull b, ull c) {
    ull d;
    asm("fma.rn.f32x2 %0, %1, %2, %3;" : "=l"(d) : "l"(a), "l"(b), "l"(c));
    return d;
}
__device__ __forceinline__ ull pack2(float x, float y) {
    ull d;
    asm("mov.b64 %0, {%1, %2};" : "=l"(d) : "f"(x), "f"(y));
    return d;
}
__device__ __forceinline__ float2 unpack2(ull v) {
    float2 r;
    asm("mov.b64 {%0, %1}, %2;" : "=f"(r.x), "=f"(r.y) : "l"(v));
    return r;
}

// ---------------------------------------------------------------------------
// Stage 1: 11x11 conv (1->8 ch) on both input planes + spike/WTA logic.
// Block (32,4), tile 32x16, 4 rows/thread (rows ty+4k). Small blocks shrink
// the wave tail (per-block duration halves -> tail loss ~13% -> ~6.5%).
// Boolean epilogue: inputs >= 0 so vm*(pe-1.5*no) >= 1 <=> pe & !no & (vm>=1);
// the spike/WTA block is pure SETP+LOP, no fp math.
// Also zeroes this batch's d_out plane and publishes the tile OR-mask.
// ---------------------------------------------------------------------------
__global__ __launch_bounds__(128, 4)
void stage1_kernel(const float* __restrict__ inp, const float* __restrict__ Wb,
                   float* __restrict__ out)
{
    __shared__ ull s01[26][44];                  // (in0,in1) packed (9.2 KB)
    __shared__ __align__(16) ull dsh[121 * 8];   // dup weights [t][f] (7.7 KB)

    const int b  = blockIdx.z;
    const int x0 = blockIdx.x * 32;
    const int y0 = blockIdx.y * 16;
    const int tx = threadIdx.x;      // 0..31
    const int ty = threadIdx.y;      // 0..3
    const int tid = ty * 32 + tx;

    for (int i = tid; i < 968; i += 128) {
        int t = i >> 3, f = i & 7;
        float w = Wb[f * 121 + t];
        dsh[i] = pack2(w, w);
    }

    const float* __restrict__ in0 = inp + ((size_t)b * 2 + 0) * HH * WW;
    const float* __restrict__ in1 = inp + ((size_t)b * 2 + 1) * HH * WW;

    for (int ry = ty; ry < 26; ry += 4) {
        int gy = y0 - 5 + ry;
        for (int rx = tx; rx < 42; rx += 32) {
            int gx = x0 - 5 + rx;
            bool ok = ((unsigned)gy < HH) && ((unsigned)gx < WW);
            float v0 = ok ? in0[gy * WW + gx] : 0.0f;
            float v1 = ok ? in1[gy * WW + gx] : 0.0f;
            s01[ry][rx] = pack2(v0, v1);
        }
    }
    __syncthreads();

    ull acc[4][8];                   // [row k][filter], .x=pos conv .y=neg conv
    #pragma unroll
    for (int k = 0; k < 4; ++k)
        #pragma unroll
        for (int f = 0; f < 8; ++f) acc[k][f] = 0ull;

    #pragma unroll 1
    for (int dy = 0; dy < 11; ++dy) {
        #pragma unroll
        for (int dx = 0; dx < 11; ++dx) {
            ull x0v = s01[ty      + dy][tx + dx];
            ull x1v = s01[ty +  4 + dy][tx + dx];
            ull x2v = s01[ty +  8 + dy][tx + dx];
            ull x3v = s01[ty + 12 + dy][tx + dx];
            const int t = dy * 11 + dx;
            const ulonglong2* wp = (const ulonglong2*)&dsh[t * 8];
            #pragma unroll
            for (int fp = 0; fp < 4; ++fp) {
                ulonglong2 w2 = wp[fp];
                acc[0][2*fp]   = ffma2(w2.x, x0v, acc[0][2*fp]);
                acc[1][2*fp]   = ffma2(w2.x, x1v, acc[1][2*fp]);
                acc[2][2*fp]   = ffma2(w2.x, x2v, acc[2][2*fp]);
                acc[3][2*fp]   = ffma2(w2.x, x3v, acc[3][2*fp]);
                acc[0][2*fp+1] = ffma2(w2.y, x0v, acc[0][2*fp+1]);
                acc[1][2*fp+1] = ffma2(w2.y, x1v, acc[1][2*fp+1]);
                acc[2][2*fp+1] = ffma2(w2.y, x2v, acc[2][2*fp+1]);
                acc[3][2*fp+1] = ffma2(w2.y, x3v, acc[3][2*fp+1]);
            }
        }
    }

    uint32_t myor = 0;
    #pragma unroll
    for (int k = 0; k < 4; ++k) {
        const int yy = ty + k * 4;
        float2 ctr = unpack2(s01[yy + 5][tx + 5]);
        bool V = (ctr.x + ctr.y) >= 1.0f;

        int b13[4], b24[4];
        #pragma unroll
        for (int o = 0; o < 4; ++o) {
            float2 e = unpack2(acc[k][2*o]);      // .x=pos even, .y=neg even
            float2 d = unpack2(acc[k][2*o+1]);    // .x=pos odd,  .y=neg odd
            bool pe = e.x >= 1.0f;
            bool ne = e.y >= 1.0f;
            bool po = d.x >= 1.0f;
            bool no = d.y >= 1.0f;
            int s1 = (pe && !no && V) ? 1 : 0;
            int s2 = (ne && !po && V) ? 1 : 0;
            int s3 = (po && !ne && V) ? 1 : 0;
            int s4 = (no && !pe && V) ? 1 : 0;
            b13[o] = s1 + s2;
            b24[o] = s3 + s4;
        }

        int tmax = 0;
        #pragma unroll
        for (int o = 0; o < 4; ++o) {
            int d = b13[o] - b24[o];
            int tp = d < 0 ? -d : d;
            if (tp > tmax) tmax = tp;
        }

        uint32_t word = 0;
        #pragma unroll
        for (int o = 0; o < 4; ++o) {
            int d = b13[o] - b24[o];
            int tp = d < 0 ? -d : d;
            uint32_t nib = 0;
            if (tp == tmax) {
                if (d >= 1)
                    nib = (uint32_t)b13[o] | ((uint32_t)b24[o] << 2);
                else if (d <= -1)
                    nib = ((uint32_t)b24[o] << 4) | ((uint32_t)b13[o] << 6);
            }
            word |= nib << (8 * o);
        }
        const size_t pix = ((size_t)b * HH + (y0 + yy)) * WW + (x0 + tx);
        g_border[pix] = word;
        out[pix] = 0.0f;   // zero-init for stage2's atomic accumulation
        myor |= word;
    }

    // Publish this 32x16 tile's OR so stage2 can skip before loading anything.
    uint32_t tileor = (uint32_t)__syncthreads_or((int)myor);
    if (tid == 0)
        g_tilemask[b * 512 + blockIdx.y * 16 + blockIdx.x] = tileor;
}

// ---------------------------------------------------------------------------
// Stage 2: depthwise 23x23 conv + spike combination. ONE (tile, group) per
// block. EARLY SKIP: probe <=21 tile-mask words covering the halo; if this
// group's nibble is zero there, exit before loading weights or halo.
// Block (32,4), tile 32x64, 16 output rows/thread, rolling window +
// depth-1 weight prefetch. Results combine via predicated atomicAdd.
// ---------------------------------------------------------------------------
__global__ __launch_bounds__(128)
void stage2_kernel(const float* __restrict__ Wg, float* __restrict__ out)
{
    __shared__ ull sh[86][55];    // decoded (chanA, chanB) pairs (37.8 KB)
    __shared__ ull wsh[529];      // duplicated weights (4.2 KB)

    const int zz  = blockIdx.z;          // 0..31 = b*8 + grp
    const int b   = zz >> 3;
    const int grp = zz & 7;
    const int x0 = blockIdx.x * 32;
    const int y0 = blockIdx.y * 64;
    const int tx = threadIdx.x;   // 0..31
    const int ty = threadIdx.y;   // 0..3
    const int tid = ty * 32 + tx;
    const int yb = ty * 16;
    const int shift = grp * 4;

    // ---- mask probe: OR the <=21 tile-masks (32x16 each) over the halo ----
    {
        const int txl = (x0 >= 11 ? x0 - 11 : 0) >> 5;
        const int txh = ((x0 + 42 < WW ? x0 + 42 : WW - 1)) >> 5;
        const int tyl = (y0 >= 11 ? y0 - 11 : 0) >> 4;
        const int tyh = ((y0 + 74 < HH ? y0 + 74 : HH - 1)) >> 4;
        const int nx = txh - txl + 1;            // <=3
        const int nt = nx * (tyh - tyl + 1);     // <=21
        uint32_t m = 0;
        if (tid < nt) {
            int tyi = tyl + tid / nx;
            int txi = txl + tid % nx;
            m = g_tilemask[b * 512 + tyi * 16 + txi];
        }
        int any = __syncthreads_or((int)((m >> shift) & 0xFu));
        if (!any) return;   // group empty over whole halo -> output untouched
    }

    const uint32_t* __restrict__ bor = g_border + (size_t)b * HH * WW;

    for (int i = tid; i < 529; i += 128) {
        float w = Wg[grp * 2 * 529 + i];
        wsh[i] = pack2(w, w);
    }

    for (int ry = ty; ry < 86; ry += 4) {
        int gy = y0 - 11 + ry;
        for (int rx = tx; rx < 54; rx += 32) {
            int gx = x0 - 11 + rx;
            uint32_t v = 0;
            if (((unsigned)gy < HH) && ((unsigned)gx < WW)) v = bor[gy * WW + gx];
            sh[ry][rx] = pack2((float)((v >> shift) & 3u),
                               (float)((v >> (shift + 2)) & 3u));
        }
    }
    __syncthreads();

    ull a[16];
    #pragma unroll
    for (int o = 0; o < 16; ++o) a[o] = 0ull;

    #pragma unroll 1
    for (int dx = 0; dx < 23; ++dx) {
        const int c = tx + dx;

        ull r[16];
        #pragma unroll
        for (int o = 0; o < 16; ++o) r[o] = sh[yb + o][c];

        ull w0 = wsh[dx];   // weight for dy=0
        #pragma unroll
        for (int dy = 0; dy < 23; ++dy) {
            ull wn = (dy < 22) ? wsh[(dy + 1) * 23 + dx] : 0ull;
            #pragma unroll
            for (int o = 0; o < 16; ++o) a[o] = ffma2(w0, r[o], a[o]);
            if (dy < 22) {
                #pragma unroll
                for (int o = 0; o < 15; ++o) r[o] = r[o + 1];
                r[15] = sh[yb + dy + 16][c];
            }
            w0 = wn;
        }
    }

    #pragma unroll
    for (int o = 0; o < 16; ++o) {
        float2 v = unpack2(a[o]);
        if (v.x >= 1.0f && v.y < 1.0f)
            atomicAdd(&out[((size_t)b * HH + (y0 + yb + o)) * WW + x0 + tx], 1.0f);
    }
}

// ---------------------------------------------------------------------------
extern "C" void kernel_launch(void* const* d_in, const int* in_sizes, int n_in,
                              void* d_out, int out_size)
{
    const float* inp = nullptr;
    const float* Wb  = nullptr;
    const float* Wg  = nullptr;
    for (int i = 0; i < n_in; ++i) {
        if (in_sizes[i] == NB * 2 * HH * WW) inp = (const float*)d_in[i];
        else if (in_sizes[i] == 8 * 121)     Wb  = (const float*)d_in[i];
        else if (in_sizes[i] == 16 * 529)    Wg  = (const float*)d_in[i];
    }

    dim3 grid1(WW / 32, HH / 16, NB);        // 32x16 tiles
    dim3 blk1(32, 4);
    stage1_kernel<<<grid1, blk1>>>(inp, Wb, (float*)d_out);

    dim3 grid2(WW / 32, HH / 64, NB * 8);    // one (32x64 tile, group) per block
    dim3 blk2(32, 4);
    stage2_kernel<<<grid2, blk2>>>(Wg, (float*)d_out);
}